// round 11
// baseline (speedup 1.0000x reference)
#include <cuda_runtime.h>
#include <cuda_fp16.h>
#include <mma.h>
#include <cstdint>

using namespace nvcuda;

#define N_IN   256
#define N_H    128
#define MAX_NODES 100000
#define MAX_EDGES 800000

// ---------------- scratch (allocation-free: __device__ globals) ----------------
// Interleaved fp16 features: H[node][set][128], set in {0,1}.  +256 pad rows.
__device__ __half g_Hh[(2u * MAX_NODES + 256) * N_H];
__device__ __half g_Wf[N_IN * N_H];                     // W in fp16
__device__ float g_wsum[N_H];
__device__ float g_bsum;
// CSR scratch (g_deg zero at t=0 via static init; re-zeroed each run by scan_add)
__device__ int   g_deg[MAX_NODES + 1];
__device__ int   g_rowptr[MAX_NODES + 1];
__device__ int   g_fill[MAX_NODES];
__device__ int   g_blk[128];
__device__ int2  g_epack[MAX_EDGES];    // (col, weight bits) packed per edge

// =======================================================================
//  Launch 0: hist + prep fused.
//  All blocks: edge histogram. Blocks 0..127: W -> fp16. Block 0: wsum/bsum.
// =======================================================================
__global__ __launch_bounds__(256) void hist_prep_kernel(
    const int* __restrict__ ei, int n_edges,
    const float* __restrict__ linW, const float* __restrict__ linb,
    const float* __restrict__ W)
{
    int i = blockIdx.x * 256 + threadIdx.x;
    if (i < n_edges) atomicAdd(&g_deg[__ldg(ei + i)], 1);

    if (blockIdx.x < 128) {
        int gi = blockIdx.x * 256 + threadIdx.x;     // 32768 = N_IN*N_H
        g_Wf[gi] = __float2half_rn(__ldg(W + gi));
    }
    if (blockIdx.x != 0) return;

    int tid  = threadIdx.x;
    int warp = tid >> 5, lane = tid & 31;
    for (int k = warp; k < N_H; k += 8) {
        float s = 0.f;
        #pragma unroll
        for (int j = lane; j < N_H; j += 32) s += linW[k * N_H + j];
        #pragma unroll
        for (int o = 16; o > 0; o >>= 1) s += __shfl_down_sync(0xffffffffu, s, o);
        if (lane == 0) g_wsum[k] = s;
    }
    __shared__ float sb[256];
    sb[tid] = (tid < N_H) ? linb[tid] : 0.f;
    __syncthreads();
    for (int o = 128; o > 0; o >>= 1) { if (tid < o) sb[tid] += sb[tid + o]; __syncthreads(); }
    if (tid == 0) g_bsum = sb[0];
}

// =======================================================================
//  Launch 1: block-wise exclusive scan of degrees
// =======================================================================
__global__ __launch_bounds__(1024) void scan_partial_kernel(int n, int n1)
{
    int tid  = threadIdx.x;
    int gid  = blockIdx.x * 1024 + tid;
    int lane = tid & 31, wid = tid >> 5;
    int v = (gid < n) ? g_deg[gid] : 0;
    int inc = v;
    #pragma unroll
    for (int o = 1; o < 32; o <<= 1) {
        int t = __shfl_up_sync(0xffffffffu, inc, o);
        if (lane >= o) inc += t;
    }
    __shared__ int ws[32];
    if (lane == 31) ws[wid] = inc;
    __syncthreads();
    if (wid == 0) {
        int s = ws[lane];
        #pragma unroll
        for (int o = 1; o < 32; o <<= 1) {
            int t = __shfl_up_sync(0xffffffffu, s, o);
            if (lane >= o) s += t;
        }
        ws[lane] = s;
    }
    __syncthreads();
    int woff = wid ? ws[wid - 1] : 0;
    int excl = woff + inc - v;
    if (gid < n1) g_rowptr[gid] = excl;
    if (tid == 1023) g_blk[blockIdx.x] = woff + inc;
}

// =======================================================================
//  Launch 2: add block carries (computed in-block), publish fill, re-zero deg
// =======================================================================
__global__ __launch_bounds__(1024) void scan_add_kernel(int n, int n1)
{
    // block-carry: sum of g_blk[0..bid) computed by warp 0, broadcast via smem
    __shared__ int s_carry;
    int tid = threadIdx.x, lane = tid & 31;
    if (tid < 32) {
        int c = 0;
        for (int b = lane; b < (int)blockIdx.x; b += 32) c += g_blk[b];
        #pragma unroll
        for (int o = 16; o > 0; o >>= 1) c += __shfl_down_sync(0xffffffffu, c, o);
        if (lane == 0) s_carry = c;
    }
    __syncthreads();
    int carry = s_carry;

    int gid = blockIdx.x * 1024 + tid;
    if (gid < n1) {
        int r = g_rowptr[gid] + carry;
        g_rowptr[gid] = r;
        if (gid < n) g_fill[gid] = r;
        g_deg[gid] = 0;
    }
}

// =======================================================================
//  Launch 3: scatter edges into packed CSR
// =======================================================================
__global__ void scatter_kernel(const int* __restrict__ ei, const float* __restrict__ ew,
                               int n_edges)
{
    int i = blockIdx.x * blockDim.x + threadIdx.x;
    if (i >= n_edges) return;
    int   r = __ldg(ei + i);
    int   c = __ldg(ei + n_edges + i);
    float w = __ldg(ew + i);
    int p = atomicAdd(&g_fill[r], 1);
    g_epack[p] = make_int2(c, __float_as_int(w));
}

// =======================================================================
//  Launch 4: GEMM g_Hh = fp16([x1;x2]) @ fp16(W), interleaved output layout
// =======================================================================
#define A_LD 72

__global__ __launch_bounds__(256) void gemm_wmma_kernel(
    const float* __restrict__ x1, const float* __restrict__ x2, int n_nodes)
{
    __shared__ __half Ah[128][A_LD];
    __shared__ float stage[8][16 * 16 + 8];

    const int m_tot = 2 * n_nodes;
    const int tid = threadIdx.x;
    const int wid = tid >> 5, lid = tid & 31;
    const int warp_m = wid & 1;
    const int warp_n = wid >> 1;
    const int blockRow = blockIdx.x * 128;

    wmma::fragment<wmma::accumulator, 16, 16, 16, float> acc[4][2];
    #pragma unroll
    for (int mi = 0; mi < 4; mi++)
        #pragma unroll
        for (int ni = 0; ni < 2; ni++)
            wmma::fill_fragment(acc[mi][ni], 0.f);

    float4 pre[8];

    #pragma unroll
    for (int t = 0; t < 8; t++) {
        int e   = t * 256 + tid;
        int row = e >> 4, c4 = e & 15;
        int mg  = blockRow + row;
        pre[t] = make_float4(0.f, 0.f, 0.f, 0.f);
        if (mg < m_tot) {
            const float* src = (mg < n_nodes)
                ? (x1 + (size_t)mg * N_IN)
                : (x2 + (size_t)(mg - n_nodes) * N_IN);
            pre[t] = *reinterpret_cast<const float4*>(src + c4 * 4);
        }
    }

    for (int ch = 0; ch < 4; ch++) {
        #pragma unroll
        for (int t = 0; t < 8; t++) {
            int e   = t * 256 + tid;
            int row = e >> 4, c4 = e & 15;
            float4 v = pre[t];
            __half2 h01 = __floats2half2_rn(v.x, v.y);
            __half2 h23 = __floats2half2_rn(v.z, v.w);
            uint2 pk;
            pk.x = *reinterpret_cast<uint32_t*>(&h01);
            pk.y = *reinterpret_cast<uint32_t*>(&h23);
            *reinterpret_cast<uint2*>(&Ah[row][c4 * 4]) = pk;
        }
        __syncthreads();

        if (ch < 3) {
            const int k0n = (ch + 1) * 64;
            #pragma unroll
            for (int t = 0; t < 8; t++) {
                int e   = t * 256 + tid;
                int row = e >> 4, c4 = e & 15;
                int mg  = blockRow + row;
                pre[t] = make_float4(0.f, 0.f, 0.f, 0.f);
                if (mg < m_tot) {
                    const float* src = (mg < n_nodes)
                        ? (x1 + (size_t)mg * N_IN)
                        : (x2 + (size_t)(mg - n_nodes) * N_IN);
                    pre[t] = *reinterpret_cast<const float4*>(src + k0n + c4 * 4);
                }
            }
        }

        const int k0 = ch * 64;
        #pragma unroll
        for (int ks = 0; ks < 4; ks++) {
            const int kk = ks * 16;
            wmma::fragment<wmma::matrix_a, 16, 16, 16, __half, wmma::row_major> af[4];
            #pragma unroll
            for (int mi = 0; mi < 4; mi++) {
                int r0 = warp_m * 64 + mi * 16;
                wmma::load_matrix_sync(af[mi], &Ah[r0][kk], A_LD);
            }
            #pragma unroll
            for (int ni = 0; ni < 2; ni++) {
                int c0 = warp_n * 32 + ni * 16;
                wmma::fragment<wmma::matrix_b, 16, 16, 16, __half, wmma::row_major> bf;
                wmma::load_matrix_sync(bf, g_Wf + (size_t)(k0 + kk) * N_H + c0, N_H);
                #pragma unroll
                for (int mi = 0; mi < 4; mi++)
                    wmma::mma_sync(acc[mi][ni], af[mi], bf, acc[mi][ni]);
            }
        }
        __syncthreads();
    }

    // ---- epilogue: interleaved store H[node][set][128] (pad absorbs overflow) ----
    #pragma unroll
    for (int mi = 0; mi < 4; mi++) {
        #pragma unroll
        for (int ni = 0; ni < 2; ni++) {
            wmma::store_matrix_sync(&stage[wid][0], acc[mi][ni], 16, wmma::mem_row_major);
            __syncwarp();
            int r    = lid >> 1;
            int cseg = (lid & 1) * 8;
            float4 f0 = *reinterpret_cast<const float4*>(&stage[wid][r * 16 + cseg]);
            float4 f1 = *reinterpret_cast<const float4*>(&stage[wid][r * 16 + cseg + 4]);
            __half2 q0 = __floats2half2_rn(f0.x, f0.y);
            __half2 q1 = __floats2half2_rn(f0.z, f0.w);
            __half2 q2 = __floats2half2_rn(f1.x, f1.y);
            __half2 q3 = __floats2half2_rn(f1.z, f1.w);
            int mg = blockRow + warp_m * 64 + mi * 16 + r;
            int gc = warp_n * 32 + ni * 16 + cseg;
            size_t off = (mg < n_nodes)
                ? ((size_t)mg * 256 + gc)
                : ((size_t)(mg - n_nodes) * 256 + 128 + gc);
            uint4 pk;
            pk.x = *reinterpret_cast<uint32_t*>(&q0);
            pk.y = *reinterpret_cast<uint32_t*>(&q1);
            pk.z = *reinterpret_cast<uint32_t*>(&q2);
            pk.w = *reinterpret_cast<uint32_t*>(&q3);
            *reinterpret_cast<uint4*>(g_Hh + off) = pk;
            __syncwarp();
        }
    }
}

// =======================================================================
//  Launch 5: fused gather + epilogue. Warp per row; ONE 512B load per edge
//  (interleaved layout). Lanes 0-15 accumulate set 0, lanes 16-31 set 1.
// =======================================================================
__device__ __forceinline__ void acc_h16(float4& lo, float4& hi, uint4 p, float wgt)
{
    float2 u0 = __half22float2(*reinterpret_cast<__half2*>(&p.x));
    float2 u1 = __half22float2(*reinterpret_cast<__half2*>(&p.y));
    float2 u2 = __half22float2(*reinterpret_cast<__half2*>(&p.z));
    float2 u3 = __half22float2(*reinterpret_cast<__half2*>(&p.w));
    lo.x += wgt * u0.x;  lo.y += wgt * u0.y;
    lo.z += wgt * u1.x;  lo.w += wgt * u1.y;
    hi.x += wgt * u2.x;  hi.y += wgt * u2.y;
    hi.z += wgt * u3.x;  hi.w += wgt * u3.y;
}

__global__ __launch_bounds__(256) void gather_final_kernel(
    const float* __restrict__ bias, const float* __restrict__ pa,
    float* __restrict__ out, int n_nodes)
{
    int row  = (blockIdx.x * blockDim.x + threadIdx.x) >> 5;
    int lane = threadIdx.x & 31;
    if (row >= n_nodes) return;

    int s = __ldg(&g_rowptr[row]);
    int e = __ldg(&g_rowptr[row + 1]);

    float4 alo = make_float4(0.f, 0.f, 0.f, 0.f);
    float4 ahi = make_float4(0.f, 0.f, 0.f, 0.f);

    int j = s;
    for (; j + 3 < e; j += 4) {
        int2 e0 = __ldg(&g_epack[j]);
        int2 e1 = __ldg(&g_epack[j + 1]);
        int2 e2 = __ldg(&g_epack[j + 2]);
        int2 e3 = __ldg(&g_epack[j + 3]);
        uint4 p0 = __ldg(reinterpret_cast<const uint4*>(g_Hh + (size_t)e0.x * 256) + lane);
        uint4 p1 = __ldg(reinterpret_cast<const uint4*>(g_Hh + (size_t)e1.x * 256) + lane);
        uint4 p2 = __ldg(reinterpret_cast<const uint4*>(g_Hh + (size_t)e2.x * 256) + lane);
        uint4 p3 = __ldg(reinterpret_cast<const uint4*>(g_Hh + (size_t)e3.x * 256) + lane);
        acc_h16(alo, ahi, p0, __int_as_float(e0.y));
        acc_h16(alo, ahi, p1, __int_as_float(e1.y));
        acc_h16(alo, ahi, p2, __int_as_float(e2.y));
        acc_h16(alo, ahi, p3, __int_as_float(e3.y));
    }
    for (; j < e; j++) {
        int2 e0 = __ldg(&g_epack[j]);
        uint4 p0 = __ldg(reinterpret_cast<const uint4*>(g_Hh + (size_t)e0.x * 256) + lane);
        acc_h16(alo, ahi, p0, __int_as_float(e0.y));
    }

    // lane covers features f..f+7 of its set (f = (lane&15)*8)
    int f = (lane & 15) * 8;
    float  a  = __ldg(pa);
    float4 b0 = *reinterpret_cast<const float4*>(bias + f);
    float4 b1 = *reinterpret_cast<const float4*>(bias + f + 4);
    float4 w0 = *reinterpret_cast<const float4*>(g_wsum + f);
    float4 w1 = *reinterpret_cast<const float4*>(g_wsum + f + 4);

    float s1 = 0.f, t;
    t = alo.x + b0.x; t = (t >= 0.f) ? t : a * t; s1 += t * w0.x;
    t = alo.y + b0.y; t = (t >= 0.f) ? t : a * t; s1 += t * w0.y;
    t = alo.z + b0.z; t = (t >= 0.f) ? t : a * t; s1 += t * w0.z;
    t = alo.w + b0.w; t = (t >= 0.f) ? t : a * t; s1 += t * w0.w;
    t = ahi.x + b1.x; t = (t >= 0.f) ? t : a * t; s1 += t * w1.x;
    t = ahi.y + b1.y; t = (t >= 0.f) ? t : a * t; s1 += t * w1.y;
    t = ahi.z + b1.z; t = (t >= 0.f) ? t : a * t; s1 += t * w1.z;
    t = ahi.w + b1.w; t = (t >= 0.f) ? t : a * t; s1 += t * w1.w;

    // reduce within each 16-lane segment (set 0: lanes 0-15, set 1: lanes 16-31)
    #pragma unroll
    for (int o = 8; o > 0; o >>= 1) s1 += __shfl_down_sync(0xffffffffu, s1, o, 16);

    if ((lane & 15) == 0)
        out[row + (lane >> 4) * n_nodes] = s1 + g_bsum;
}

// =======================================================================
//  launcher — 6 serial launches; -s 5 profiles the gather
// =======================================================================
extern "C" void kernel_launch(void* const* d_in, const int* in_sizes, int n_in,
                              void* d_out, int out_size)
{
    const float* x1 = (const float*)d_in[0];
    const float* x2 = (const float*)d_in[1];
    const int*   ei = (const int*)  d_in[2];
    const float* ew = (const float*)d_in[3];
    const float* Wg = (const float*)d_in[4];
    const float* gb = (const float*)d_in[5];
    const float* pa = (const float*)d_in[6];
    const float* lW = (const float*)d_in[7];
    const float* lb = (const float*)d_in[8];
    float* out = (float*)d_out;

    const int n_nodes = in_sizes[0] / N_IN;        // 100000
    const int n_edges = in_sizes[3];               // 800000
    const int m_tot   = 2 * n_nodes;
    const int n1      = n_nodes + 1;
    const int nb      = (n1 + 1023) / 1024;        // <=98

    hist_prep_kernel<<<(n_edges + 255) / 256, 256>>>(ei, n_edges, lW, lb, Wg);
    scan_partial_kernel<<<nb, 1024>>>(n_nodes, n1);
    scan_add_kernel<<<nb, 1024>>>(n_nodes, n1);
    scatter_kernel<<<(n_edges + 255) / 256, 256>>>(ei, ew, n_edges);
    gemm_wmma_kernel<<<(m_tot + 127) / 128, 256>>>(x1, x2, n_nodes);
    {
        long long threads = (long long)n_nodes * 32;
        int blocks = (int)((threads + 255) / 256);
        gather_final_kernel<<<blocks, 256>>>(gb, pa, out, n_nodes);
    }
}